// round 1
// baseline (speedup 1.0000x reference)
#include <cuda_runtime.h>
#include <cuda_bf16.h>

#define N_NODES 100000
#define N_EDGES 1600000
#define FEAT    128

// ---------------- device scratch (no allocations allowed) ----------------
__device__ float g_bufA[N_NODES * FEAT];
__device__ float g_bufB[N_NODES * FEAT];
__device__ int   g_rowstart[N_NODES + 1];
__device__ int   g_cursor[N_NODES];
__device__ float g_invdeg[N_NODES];
__device__ int   g_csr_src[N_EDGES];

// ---------------- helpers ----------------
union F2U { float2 f; unsigned long long u; };

__device__ __forceinline__ float2 ffma2(float2 a, float2 b, float2 c) {
    F2U ua, ub, uc, ud;
    ua.f = a; ub.f = b; uc.f = c;
    asm("fma.rn.f32x2 %0, %1, %2, %3;" : "=l"(ud.u) : "l"(ua.u), "l"(ub.u), "l"(uc.u));
    return ud.f;
}

__device__ __forceinline__ float4 f4add(float4 a, float4 b) {
    return make_float4(a.x + b.x, a.y + b.y, a.z + b.z, a.w + b.w);
}

// ---------------- CSR build ----------------
__global__ void zero_cursor_kernel() {
    int i = blockIdx.x * blockDim.x + threadIdx.x;
    if (i < N_NODES) g_cursor[i] = 0;
}

__global__ void hist_kernel(const int* __restrict__ dst) {
    int e = blockIdx.x * blockDim.x + threadIdx.x;
    if (e < N_EDGES) atomicAdd(&g_cursor[dst[e]], 1);
}

// single-block exclusive scan over the degree histogram.
// Also produces inv_deg and resets g_cursor to the row starts for the scatter pass.
__global__ void scan_kernel() {
    __shared__ int sh[1024];
    int carry = 0;
    for (int base = 0; base < N_NODES; base += 1024) {
        int i = base + threadIdx.x;
        int v = (i < N_NODES) ? g_cursor[i] : 0;
        sh[threadIdx.x] = v;
        __syncthreads();
        #pragma unroll
        for (int off = 1; off < 1024; off <<= 1) {
            int x = (threadIdx.x >= (unsigned)off) ? sh[threadIdx.x - off] : 0;
            __syncthreads();
            sh[threadIdx.x] += x;
            __syncthreads();
        }
        if (i < N_NODES) {
            int excl = carry + sh[threadIdx.x] - v;  // exclusive prefix
            g_rowstart[i] = excl;
            g_cursor[i]   = excl;
            g_invdeg[i]   = 1.0f / fmaxf((float)v, 1.0f);
        }
        carry += sh[1023];
        __syncthreads();
    }
    if (threadIdx.x == 0) g_rowstart[N_NODES] = carry;
}

__global__ void scatter_kernel(const int* __restrict__ src, const int* __restrict__ dst) {
    int e = blockIdx.x * blockDim.x + threadIdx.x;
    if (e < N_EDGES) {
        int pos = atomicAdd(&g_cursor[dst[e]], 1);
        g_csr_src[pos] = src[e];
    }
}

// ---------------- aggregation: out = h + inv_deg * sum_{src in-edges} h[src] ----------------
// One warp per dst node; each lane owns one float4 (4 of the 128 features).
__global__ void agg_kernel(const float4* __restrict__ h4, float4* __restrict__ out4) {
    int warp = (blockIdx.x * blockDim.x + threadIdx.x) >> 5;
    if (warp >= N_NODES) return;
    int lane = threadIdx.x & 31;

    int s = g_rowstart[warp];
    int e = g_rowstart[warp + 1];

    float4 acc = make_float4(0.f, 0.f, 0.f, 0.f);
    int i = s;
    // 4-way unroll for memory-level parallelism (independent src rows)
    for (; i + 4 <= e; i += 4) {
        int s0 = g_csr_src[i + 0];
        int s1 = g_csr_src[i + 1];
        int s2 = g_csr_src[i + 2];
        int s3 = g_csr_src[i + 3];
        float4 v0 = h4[s0 * 32 + lane];
        float4 v1 = h4[s1 * 32 + lane];
        float4 v2 = h4[s2 * 32 + lane];
        float4 v3 = h4[s3 * 32 + lane];
        acc = f4add(acc, f4add(f4add(v0, v1), f4add(v2, v3)));
    }
    for (; i < e; i++) {
        int s0 = g_csr_src[i];
        acc = f4add(acc, h4[s0 * 32 + lane]);
    }

    float w = g_invdeg[warp];
    float4 self = h4[warp * 32 + lane];
    float4 o;
    o.x = self.x + acc.x * w;
    o.y = self.y + acc.y * w;
    o.z = self.z + acc.z * w;
    o.w = self.w + acc.w * w;
    out4[warp * 32 + lane] = o;
}

// ---------------- GEMM: out[M,128] = [relu](A[M,128] @ W[128,128] + b) ----------------
// Block tile 128 rows x 128 cols (full N, full K). 256 threads, 8x8 register tile,
// packed fma.rn.f32x2 for 2x fp32 throughput. Dynamic smem: A tile + W + bias.
#define GEMM_SMEM_BYTES ((2 * 128 * 128 + 128) * 4)

__global__ void gemm_kernel(const float* __restrict__ A,
                            const float* __restrict__ W,
                            const float* __restrict__ bias,
                            float* __restrict__ out,
                            int M, int do_relu) {
    extern __shared__ float smem[];
    float* sA = smem;                 // 128*128
    float* sW = smem + 128 * 128;     // 128*128
    float* sB = smem + 2 * 128 * 128; // 128

    const int tid  = threadIdx.x;
    const int row0 = blockIdx.x * 128;
    const int rows = min(128, M - row0);

    // load W (coalesced float4)
    {
        const float4* W4 = reinterpret_cast<const float4*>(W);
        float4* sW4 = reinterpret_cast<float4*>(sW);
        #pragma unroll
        for (int idx = tid; idx < 128 * 128 / 4; idx += 256) sW4[idx] = W4[idx];
    }
    // bias
    if (tid < 32) {
        reinterpret_cast<float4*>(sB)[tid] = reinterpret_cast<const float4*>(bias)[tid];
    }
    // A tile (guarded rows)
    {
        const float4* A4 = reinterpret_cast<const float4*>(A) + row0 * 32;
        float4* sA4 = reinterpret_cast<float4*>(sA);
        for (int idx = tid; idx < rows * 32; idx += 256) sA4[idx] = A4[idx];
    }
    __syncthreads();

    const int tx = tid & 15;   // col group: cols tx*8 .. tx*8+7
    const int ty = tid >> 4;   // row group: rows ty*8 .. ty*8+7

    float2 acc[8][4];
    #pragma unroll
    for (int m = 0; m < 8; m++)
        #pragma unroll
        for (int n = 0; n < 4; n++) acc[m][n] = make_float2(0.f, 0.f);

    const float* aPtr = sA + (ty * 8) * 128;
    const float* wPtr = sW + tx * 8;

    for (int k = 0; k < 128; k += 4) {
        float4 av[8];
        #pragma unroll
        for (int m = 0; m < 8; m++)
            av[m] = *reinterpret_cast<const float4*>(aPtr + m * 128 + k);

        #pragma unroll
        for (int kk = 0; kk < 4; kk++) {
            float4 blo = *reinterpret_cast<const float4*>(wPtr + (k + kk) * 128);
            float4 bhi = *reinterpret_cast<const float4*>(wPtr + (k + kk) * 128 + 4);
            float2 bv[4];
            bv[0] = make_float2(blo.x, blo.y);
            bv[1] = make_float2(blo.z, blo.w);
            bv[2] = make_float2(bhi.x, bhi.y);
            bv[3] = make_float2(bhi.z, bhi.w);
            #pragma unroll
            for (int m = 0; m < 8; m++) {
                float a = reinterpret_cast<const float*>(&av[m])[kk];
                float2 aa = make_float2(a, a);
                #pragma unroll
                for (int n = 0; n < 4; n++)
                    acc[m][n] = ffma2(aa, bv[n], acc[m][n]);
            }
        }
    }

    // epilogue: bias (+relu), guarded float4 stores
    float4 blo = *reinterpret_cast<const float4*>(sB + tx * 8);
    float4 bhi = *reinterpret_cast<const float4*>(sB + tx * 8 + 4);
    #pragma unroll
    for (int m = 0; m < 8; m++) {
        int r = ty * 8 + m;
        if (r < rows) {
            float4 o0, o1;
            o0.x = acc[m][0].x + blo.x;
            o0.y = acc[m][0].y + blo.y;
            o0.z = acc[m][1].x + blo.z;
            o0.w = acc[m][1].y + blo.w;
            o1.x = acc[m][2].x + bhi.x;
            o1.y = acc[m][2].y + bhi.y;
            o1.z = acc[m][3].x + bhi.z;
            o1.w = acc[m][3].y + bhi.w;
            if (do_relu) {
                o0.x = fmaxf(o0.x, 0.f); o0.y = fmaxf(o0.y, 0.f);
                o0.z = fmaxf(o0.z, 0.f); o0.w = fmaxf(o0.w, 0.f);
                o1.x = fmaxf(o1.x, 0.f); o1.y = fmaxf(o1.y, 0.f);
                o1.z = fmaxf(o1.z, 0.f); o1.w = fmaxf(o1.w, 0.f);
            }
            float* orow = out + (long)(row0 + r) * 128 + tx * 8;
            *reinterpret_cast<float4*>(orow)     = o0;
            *reinterpret_cast<float4*>(orow + 4) = o1;
        }
    }
}

// ---------------- launch ----------------
extern "C" void kernel_launch(void* const* d_in, const int* in_sizes, int n_in,
                              void* d_out, int out_size) {
    const float* x        = (const float*)d_in[0];
    const float* W1       = (const float*)d_in[1];
    const float* b1       = (const float*)d_in[2];
    const float* W2       = (const float*)d_in[3];
    const float* b2       = (const float*)d_in[4];
    const float* W3       = (const float*)d_in[5];
    const float* b3       = (const float*)d_in[6];
    const int*   edge_src = (const int*)d_in[7];
    const int*   edge_dst = (const int*)d_in[8];
    float* out = (float*)d_out;

    (void)in_sizes; (void)n_in; (void)out_size;

    cudaFuncSetAttribute(gemm_kernel,
                         cudaFuncAttributeMaxDynamicSharedMemorySize, GEMM_SMEM_BYTES);

    float* bufA; float* bufB;
    cudaGetSymbolAddress((void**)&bufA, g_bufA);
    cudaGetSymbolAddress((void**)&bufB, g_bufB);

    const int M = N_NODES;
    const int edgeBlocks = (N_EDGES + 255) / 256;
    const int nodeBlocks = (N_NODES + 255) / 256;
    const int aggBlocks  = (N_NODES * 32 + 255) / 256;
    const int gemmBlocks = (M + 127) / 128;

    // CSR build (per call; graph-replay safe, deterministic work)
    zero_cursor_kernel<<<nodeBlocks, 256>>>();
    hist_kernel<<<edgeBlocks, 256>>>(edge_dst);
    scan_kernel<<<1, 1024>>>();
    scatter_kernel<<<edgeBlocks, 256>>>(edge_src, edge_dst);

    // layer 1
    agg_kernel<<<aggBlocks, 256>>>((const float4*)x, (float4*)bufA);
    gemm_kernel<<<gemmBlocks, 256, GEMM_SMEM_BYTES>>>(bufA, W1, b1, bufB, M, 1);
    // layer 2
    agg_kernel<<<aggBlocks, 256>>>((const float4*)bufB, (float4*)bufA);
    gemm_kernel<<<gemmBlocks, 256, GEMM_SMEM_BYTES>>>(bufA, W2, b2, bufB, M, 1);
    // layer 3
    agg_kernel<<<aggBlocks, 256>>>((const float4*)bufB, (float4*)bufA);
    gemm_kernel<<<gemmBlocks, 256, GEMM_SMEM_BYTES>>>(bufA, W3, b3, out, M, 0);
}

// round 4
// speedup vs baseline: 1.0104x; 1.0104x over previous
#include <cuda_runtime.h>
#include <cuda_bf16.h>
#include <cstdint>

#define N_NODES 100000
#define N_EDGES 1600000
#define FEAT    128

// ---------------- device scratch (no allocations allowed) ----------------
__device__ float g_bufA[N_NODES * FEAT];
__device__ float g_bufB[N_NODES * FEAT];
__device__ int   g_rowstart[N_NODES + 1];
__device__ int   g_cursor[N_NODES];
__device__ float g_invdeg[N_NODES];
__device__ int   g_csr_src[N_EDGES];
__device__ __nv_bfloat16 g_whi[3 * FEAT * FEAT];   // [n][k] (K contiguous) = col-major B
__device__ __nv_bfloat16 g_wlo[3 * FEAT * FEAT];

// ---------------- helpers ----------------
__device__ __forceinline__ uint32_t smem_u32(const void* p) {
    uint32_t a;
    asm("{ .reg .u64 t; cvta.to.shared.u64 t, %1; cvt.u32.u64 %0, t; }" : "=r"(a) : "l"(p));
    return a;
}

__device__ __forceinline__ void ldmatrix_x4(uint32_t* r, uint32_t addr) {
    asm volatile("ldmatrix.sync.aligned.m8n8.x4.shared.b16 {%0,%1,%2,%3}, [%4];"
                 : "=r"(r[0]), "=r"(r[1]), "=r"(r[2]), "=r"(r[3]) : "r"(addr));
}
__device__ __forceinline__ void ldmatrix_x2(uint32_t* r, uint32_t addr) {
    asm volatile("ldmatrix.sync.aligned.m8n8.x2.shared.b16 {%0,%1}, [%2];"
                 : "=r"(r[0]), "=r"(r[1]) : "r"(addr));
}
__device__ __forceinline__ void mma16816(float* c, const uint32_t* a, const uint32_t* b) {
    asm volatile("mma.sync.aligned.m16n8k16.row.col.f32.bf16.bf16.f32 "
                 "{%0,%1,%2,%3}, {%4,%5,%6,%7}, {%8,%9}, {%0,%1,%2,%3};"
                 : "+f"(c[0]), "+f"(c[1]), "+f"(c[2]), "+f"(c[3])
                 : "r"(a[0]), "r"(a[1]), "r"(a[2]), "r"(a[3]), "r"(b[0]), "r"(b[1]));
}

// ---------------- CSR build ----------------
__global__ void zero_cursor_kernel() {
    int i = blockIdx.x * blockDim.x + threadIdx.x;
    if (i < N_NODES) g_cursor[i] = 0;
}

__global__ void hist_kernel(const int* __restrict__ dst) {
    int e = blockIdx.x * blockDim.x + threadIdx.x;
    if (e < N_EDGES) atomicAdd(&g_cursor[dst[e]], 1);
}

// chunked single-block scan: each of 1024 threads owns a contiguous chunk.
__global__ void scan_kernel() {
    __shared__ int ssum[1024];
    const int CH = (N_NODES + 1023) / 1024;  // 98
    int t = threadIdx.x;
    int lo = t * CH;
    int hi = min(lo + CH, N_NODES);
    int s = 0;
    for (int i = lo; i < hi; i++) s += g_cursor[i];
    ssum[t] = s;
    __syncthreads();
    #pragma unroll
    for (int off = 1; off < 1024; off <<= 1) {
        int v = (t >= off) ? ssum[t - off] : 0;
        __syncthreads();
        ssum[t] += v;
        __syncthreads();
    }
    int excl = ssum[t] - s;  // exclusive prefix of this chunk
    for (int i = lo; i < hi; i++) {
        int d = g_cursor[i];
        g_rowstart[i] = excl;
        g_cursor[i]   = excl;
        g_invdeg[i]   = 1.0f / fmaxf((float)d, 1.0f);
        excl += d;
    }
    if (t == 1023) g_rowstart[N_NODES] = excl;
}

__global__ void scatter_kernel(const int* __restrict__ src, const int* __restrict__ dst) {
    int e = blockIdx.x * blockDim.x + threadIdx.x;
    if (e < N_EDGES) {
        int pos = atomicAdd(&g_cursor[dst[e]], 1);
        g_csr_src[pos] = src[e];
    }
}

// ---------------- weight prep: fp32 W[k][n] -> bf16 hi/lo in [n][k] ----------------
__global__ void convw_kernel(const float* __restrict__ W1, const float* __restrict__ W2,
                             const float* __restrict__ W3) {
    int i = blockIdx.x * blockDim.x + threadIdx.x;
    if (i >= 3 * FEAT * FEAT) return;
    int l = i >> 14, r = i & 16383;
    int n = r >> 7, k = r & 127;
    const float* W = (l == 0) ? W1 : ((l == 1) ? W2 : W3);
    float v = W[k * FEAT + n];
    __nv_bfloat16 h = __float2bfloat16(v);
    g_whi[i] = h;
    g_wlo[i] = __float2bfloat16(v - __bfloat162float(h));
}

// ---------------- aggregation: out = h + inv_deg * sum_{src} h[src] ----------------
__global__ void agg_kernel(const float4* __restrict__ h4, float4* __restrict__ out4) {
    int warp = (blockIdx.x * blockDim.x + threadIdx.x) >> 5;
    if (warp >= N_NODES) return;
    int lane = threadIdx.x & 31;

    int s = g_rowstart[warp];
    int e = g_rowstart[warp + 1];

    float4 acc = make_float4(0.f, 0.f, 0.f, 0.f);
    int i = s;
    for (; i + 4 <= e; i += 4) {
        int s0 = g_csr_src[i + 0];
        int s1 = g_csr_src[i + 1];
        int s2 = g_csr_src[i + 2];
        int s3 = g_csr_src[i + 3];
        float4 v0 = h4[s0 * 32 + lane];
        float4 v1 = h4[s1 * 32 + lane];
        float4 v2 = h4[s2 * 32 + lane];
        float4 v3 = h4[s3 * 32 + lane];
        acc.x += (v0.x + v1.x) + (v2.x + v3.x);
        acc.y += (v0.y + v1.y) + (v2.y + v3.y);
        acc.z += (v0.z + v1.z) + (v2.z + v3.z);
        acc.w += (v0.w + v1.w) + (v2.w + v3.w);
    }
    for (; i < e; i++) {
        int s0 = g_csr_src[i];
        float4 v = h4[s0 * 32 + lane];
        acc.x += v.x; acc.y += v.y; acc.z += v.z; acc.w += v.w;
    }

    float w = g_invdeg[warp];
    float4 self = h4[warp * 32 + lane];
    float4 o;
    o.x = self.x + acc.x * w;
    o.y = self.y + acc.y * w;
    o.z = self.z + acc.z * w;
    o.w = self.w + acc.w * w;
    out4[warp * 32 + lane] = o;
}

// ---------------- HMMA GEMM: out[M,128] = [relu](A[M,128] @ W + b) ----------------
// bf16 hi/lo split via mma.sync (compute_103-portable): D = aHi*wHi + aHi*wLo + aLo*wHi.
// smem tiles padded to 136-elem pitch (272B) -> ldmatrix conflict-free.
#define APITCH 136
#define GEMM_SMEM_BYTES (4 * 128 * APITCH * 2)

__global__ void __launch_bounds__(256, 1)
mma_gemm_kernel(const float* __restrict__ A,
                const __nv_bfloat16* __restrict__ whi,
                const __nv_bfloat16* __restrict__ wlo,
                const float* __restrict__ bias,
                float* __restrict__ out, int M, int do_relu) {
    extern __shared__ __nv_bfloat16 sm[];
    __nv_bfloat16* sAhi = sm;
    __nv_bfloat16* sAlo = sm + 128 * APITCH;
    __nv_bfloat16* sWhi = sm + 2 * 128 * APITCH;
    __nv_bfloat16* sWlo = sm + 3 * 128 * APITCH;

    const int tid  = threadIdx.x;
    const int lane = tid & 31;
    const int wid  = tid >> 5;
    const int row0 = blockIdx.x * 128;
    const int rows = min(128, M - row0);

    // zero A tiles if partial block
    if (rows < 128) {
        uint32_t z = 0;
        uint32_t base = smem_u32(sAhi);
        for (int idx = tid; idx < 2 * 128 * APITCH / 2; idx += 256)
            asm volatile("st.shared.b32 [%0], %1;" :: "r"(base + idx * 4), "r"(z) : "memory");
        __syncthreads();
    }

    // load + convert A rows -> bf16 hi/lo
    {
        const float4* A4 = reinterpret_cast<const float4*>(A);
        for (int idx = tid; idx < rows * 32; idx += 256) {
            int r = idx >> 5, c4 = idx & 31;
            float4 a = __ldg(&A4[(size_t)(row0 + r) * 32 + c4]);
            __nv_bfloat162 h0 = __floats2bfloat162_rn(a.x, a.y);
            __nv_bfloat162 h1 = __floats2bfloat162_rn(a.z, a.w);
            float2 f0 = __bfloat1622float2(h0);
            float2 f1 = __bfloat1622float2(h1);
            __nv_bfloat162 l0 = __floats2bfloat162_rn(a.x - f0.x, a.y - f0.y);
            __nv_bfloat162 l1 = __floats2bfloat162_rn(a.z - f1.x, a.w - f1.y);
            int eoff = r * APITCH + c4 * 4;
            *reinterpret_cast<__nv_bfloat162*>(sAhi + eoff)     = h0;
            *reinterpret_cast<__nv_bfloat162*>(sAhi + eoff + 2) = h1;
            *reinterpret_cast<__nv_bfloat162*>(sAlo + eoff)     = l0;
            *reinterpret_cast<__nv_bfloat162*>(sAlo + eoff + 2) = l1;
        }
    }

    // load W hi/lo tiles ([n][k] bf16, 32KB each)
    {
        const uint4* wh4 = reinterpret_cast<const uint4*>(whi);
        const uint4* wl4 = reinterpret_cast<const uint4*>(wlo);
        for (int idx = tid; idx < 2048; idx += 256) {
            int r = idx >> 4, c16 = idx & 15;   // c16*8 elem offset
            int eoff = r * APITCH + c16 * 8;
            *reinterpret_cast<uint4*>(sWhi + eoff) = __ldg(&wh4[idx]);
            *reinterpret_cast<uint4*>(sWlo + eoff) = __ldg(&wl4[idx]);
        }
    }
    __syncthreads();

    // warp grid: 4 (m) x 2 (n); warp tile 32m x 64n
    const int wm = wid & 3;
    const int wn = wid >> 2;

    float acc[2][8][4];
    #pragma unroll
    for (int i = 0; i < 2; i++)
        #pragma unroll
        for (int j = 0; j < 8; j++)
            #pragma unroll
            for (int c = 0; c < 4; c++) acc[i][j][c] = 0.f;

    const uint32_t aRowOff = (uint32_t)(((wm * 32 + (lane & 15)) * APITCH + (lane >> 4) * 8) * 2);
    const uint32_t bRowOff = (uint32_t)(((wn * 64 + (lane & 7)) * APITCH + ((lane >> 3) & 1) * 8) * 2);

    #pragma unroll
    for (int pass = 0; pass < 3; pass++) {
        const __nv_bfloat16* pA = (pass == 2) ? sAlo : sAhi;
        const __nv_bfloat16* pW = (pass == 1) ? sWlo : sWhi;
        uint32_t aAddr = smem_u32(pA) + aRowOff;
        uint32_t bAddr = smem_u32(pW) + bRowOff;

        #pragma unroll
        for (int kk = 0; kk < 8; kk++) {
            uint32_t a0[4], a1[4];
            ldmatrix_x4(a0, aAddr + kk * 32);
            ldmatrix_x4(a1, aAddr + 16 * APITCH * 2 + kk * 32);
            #pragma unroll
            for (int tn = 0; tn < 8; tn++) {
                uint32_t b[2];
                ldmatrix_x2(b, bAddr + tn * 8 * APITCH * 2 + kk * 32);
                mma16816(acc[0][tn], a0, b);
                mma16816(acc[1][tn], a1, b);
            }
        }
    }

    // epilogue: bias + relu, float2 stores
    #pragma unroll
    for (int tm = 0; tm < 2; tm++) {
        int rbase = wm * 32 + tm * 16 + (lane >> 2);
        #pragma unroll
        for (int half = 0; half < 2; half++) {
            int r = rbase + half * 8;
            if (r < rows) {
                float* orow = out + (size_t)(row0 + r) * 128;
                #pragma unroll
                for (int tn = 0; tn < 8; tn++) {
                    int c = wn * 64 + tn * 8 + (lane & 3) * 2;
                    float2 o;
                    o.x = acc[tm][tn][half * 2 + 0] + __ldg(&bias[c + 0]);
                    o.y = acc[tm][tn][half * 2 + 1] + __ldg(&bias[c + 1]);
                    if (do_relu) { o.x = fmaxf(o.x, 0.f); o.y = fmaxf(o.y, 0.f); }
                    *reinterpret_cast<float2*>(orow + c) = o;
                }
            }
        }
    }
}

// ---------------- launch ----------------
extern "C" void kernel_launch(void* const* d_in, const int* in_sizes, int n_in,
                              void* d_out, int out_size) {
    const float* x        = (const float*)d_in[0];
    const float* W1       = (const float*)d_in[1];
    const float* b1       = (const float*)d_in[2];
    const float* W2       = (const float*)d_in[3];
    const float* b2       = (const float*)d_in[4];
    const float* W3       = (const float*)d_in[5];
    const float* b3       = (const float*)d_in[6];
    const int*   edge_src = (const int*)d_in[7];
    const int*   edge_dst = (const int*)d_in[8];
    float* out = (float*)d_out;

    (void)in_sizes; (void)n_in; (void)out_size;

    cudaFuncSetAttribute(mma_gemm_kernel,
                         cudaFuncAttributeMaxDynamicSharedMemorySize, GEMM_SMEM_BYTES);

    float* bufA; float* bufB;
    __nv_bfloat16* whi; __nv_bfloat16* wlo;
    cudaGetSymbolAddress((void**)&bufA, g_bufA);
    cudaGetSymbolAddress((void**)&bufB, g_bufB);
    cudaGetSymbolAddress((void**)&whi, g_whi);
    cudaGetSymbolAddress((void**)&wlo, g_wlo);

    const int M = N_NODES;
    const int edgeBlocks = (N_EDGES + 255) / 256;
    const int nodeBlocks = (N_NODES + 255) / 256;
    const int aggBlocks  = (N_NODES * 32 + 255) / 256;
    const int gemmBlocks = (M + 127) / 128;

    // weight prep (independent; overlaps CSR build)
    convw_kernel<<<(3 * FEAT * FEAT + 255) / 256, 256>>>(W1, W2, W3);

    // CSR build
    zero_cursor_kernel<<<nodeBlocks, 256>>>();
    hist_kernel<<<edgeBlocks, 256>>>(edge_dst);
    scan_kernel<<<1, 1024>>>();
    scatter_kernel<<<edgeBlocks, 256>>>(edge_src, edge_dst);

    // layer 1
    agg_kernel<<<aggBlocks, 256>>>((const float4*)x, (float4*)bufA);
    mma_gemm_kernel<<<gemmBlocks, 256, GEMM_SMEM_BYTES>>>(bufA, whi, wlo, b1, bufB, M, 1);
    // layer 2
    agg_kernel<<<aggBlocks, 256>>>((const float4*)bufB, (float4*)bufA);
    mma_gemm_kernel<<<gemmBlocks, 256, GEMM_SMEM_BYTES>>>(bufA, whi + FEAT * FEAT, wlo + FEAT * FEAT, b2, bufB, M, 1);
    // layer 3
    agg_kernel<<<aggBlocks, 256>>>((const float4*)bufB, (float4*)bufA);
    mma_gemm_kernel<<<gemmBlocks, 256, GEMM_SMEM_BYTES>>>(bufA, whi + 2 * FEAT * FEAT, wlo + 2 * FEAT * FEAT, b3, out, M, 0);
}

// round 5
// speedup vs baseline: 1.5234x; 1.5078x over previous
#include <cuda_runtime.h>
#include <cuda_bf16.h>
#include <cstdint>

#define N_NODES 100000
#define N_EDGES 1600000
#define FEAT    128

#define SCAN_BLK   512
#define SCAN_NBLK  ((N_NODES + SCAN_BLK - 1) / SCAN_BLK)   // 196

// ---------------- device scratch (no allocations allowed) ----------------
__device__ float g_bufA[N_NODES * FEAT];
__device__ float g_bufB[N_NODES * FEAT];
__device__ int   g_rowstart[N_NODES + 1];
__device__ int   g_cursor[N_NODES];
__device__ float g_invdeg[N_NODES];
__device__ int   g_csr_src[N_EDGES];
__device__ int   g_blksum[SCAN_NBLK];
__device__ int   g_blkoff[SCAN_NBLK];
__device__ __nv_bfloat16 g_whi[3 * FEAT * FEAT];   // [n][k] (K contiguous) = col-major B
__device__ __nv_bfloat16 g_wlo[3 * FEAT * FEAT];

// ---------------- helpers ----------------
__device__ __forceinline__ uint32_t smem_u32(const void* p) {
    uint32_t a;
    asm("{ .reg .u64 t; cvta.to.shared.u64 t, %1; cvt.u32.u64 %0, t; }" : "=r"(a) : "l"(p));
    return a;
}

__device__ __forceinline__ void ldmatrix_x4(uint32_t* r, uint32_t addr) {
    asm volatile("ldmatrix.sync.aligned.m8n8.x4.shared.b16 {%0,%1,%2,%3}, [%4];"
                 : "=r"(r[0]), "=r"(r[1]), "=r"(r[2]), "=r"(r[3]) : "r"(addr));
}
__device__ __forceinline__ void ldmatrix_x2(uint32_t* r, uint32_t addr) {
    asm volatile("ldmatrix.sync.aligned.m8n8.x2.shared.b16 {%0,%1}, [%2];"
                 : "=r"(r[0]), "=r"(r[1]) : "r"(addr));
}
__device__ __forceinline__ void mma16816(float* c, const uint32_t* a, const uint32_t* b) {
    asm volatile("mma.sync.aligned.m16n8k16.row.col.f32.bf16.bf16.f32 "
                 "{%0,%1,%2,%3}, {%4,%5,%6,%7}, {%8,%9}, {%0,%1,%2,%3};"
                 : "+f"(c[0]), "+f"(c[1]), "+f"(c[2]), "+f"(c[3])
                 : "r"(a[0]), "r"(a[1]), "r"(a[2]), "r"(a[3]), "r"(b[0]), "r"(b[1]));
}

// ---------------- CSR build ----------------
__global__ void zero_cursor_kernel() {
    int i = blockIdx.x * blockDim.x + threadIdx.x;
    if (i < N_NODES) g_cursor[i] = 0;
}

__global__ void hist_kernel(const int* __restrict__ dst) {
    int e = blockIdx.x * blockDim.x + threadIdx.x;
    if (e < N_EDGES) atomicAdd(&g_cursor[dst[e]], 1);
}

// pass 1: per-block sums of the degree histogram (coalesced, all SMs)
__global__ void scan_reduce_kernel() {
    int b = blockIdx.x;
    int i0 = b * SCAN_BLK + threadIdx.x;
    int i1 = i0 + 256;
    int v = 0;
    if (i0 < N_NODES) v += g_cursor[i0];
    if (i1 < N_NODES && (threadIdx.x + 256) < SCAN_BLK) v += g_cursor[i1];
    // warp reduce then block reduce
    #pragma unroll
    for (int off = 16; off > 0; off >>= 1) v += __shfl_down_sync(0xFFFFFFFFu, v, off);
    __shared__ int ws[8];
    int lane = threadIdx.x & 31, w = threadIdx.x >> 5;
    if (lane == 0) ws[w] = v;
    __syncthreads();
    if (w == 0) {
        int s = (lane < 8) ? ws[lane] : 0;
        #pragma unroll
        for (int off = 4; off > 0; off >>= 1) s += __shfl_down_sync(0xFFFFFFFFu, s, off);
        if (lane == 0) g_blksum[b] = s;
    }
}

// pass 2: single block scans the block sums (exclusive) and writes total
__global__ void scan_blocksums_kernel() {
    int t = threadIdx.x;  // 256 threads
    int v = (t < SCAN_NBLK) ? g_blksum[t] : 0;
    int orig = v;
    int lane = t & 31, w = t >> 5;
    #pragma unroll
    for (int off = 1; off < 32; off <<= 1) {
        int n = __shfl_up_sync(0xFFFFFFFFu, v, off);
        if (lane >= off) v += n;
    }
    __shared__ int ws[8];
    if (lane == 31) ws[w] = v;
    __syncthreads();
    if (t < 8) {
        int s = ws[t];
        #pragma unroll
        for (int off = 1; off < 8; off <<= 1) {
            int n = __shfl_up_sync(0xFFu, s, off);
            if ((t & 7) >= off) s += n;
        }
        ws[t] = s;
    }
    __syncthreads();
    int base = (w > 0) ? ws[w - 1] : 0;
    int incl = base + v;
    if (t < SCAN_NBLK) g_blkoff[t] = incl - orig;  // exclusive
    if (t == SCAN_NBLK - 1) g_rowstart[N_NODES] = incl;
}

// pass 3: block-local exclusive scan + write rowstart/cursor/invdeg (coalesced)
__global__ void scan_write_kernel() {
    int i = blockIdx.x * SCAN_BLK + threadIdx.x;   // 512 threads, 1 elem each
    int d = (i < N_NODES) ? g_cursor[i] : 0;
    int lane = threadIdx.x & 31, w = threadIdx.x >> 5;
    int v = d;
    #pragma unroll
    for (int off = 1; off < 32; off <<= 1) {
        int n = __shfl_up_sync(0xFFFFFFFFu, v, off);
        if (lane >= off) v += n;
    }
    __shared__ int ws[16];
    if (lane == 31) ws[w] = v;
    __syncthreads();
    if (threadIdx.x < 16) {
        int s = ws[threadIdx.x];
        #pragma unroll
        for (int off = 1; off < 16; off <<= 1) {
            int n = __shfl_up_sync(0xFFFFu, s, off);
            if (threadIdx.x >= off) s += n;
        }
        ws[threadIdx.x] = s;
    }
    __syncthreads();
    int base = (w > 0) ? ws[w - 1] : 0;
    int excl = g_blkoff[blockIdx.x] + base + v - d;
    if (i < N_NODES) {
        g_rowstart[i] = excl;
        g_cursor[i]   = excl;
        g_invdeg[i]   = 1.0f / fmaxf((float)d, 1.0f);
    }
}

__global__ void scatter_kernel(const int* __restrict__ src, const int* __restrict__ dst) {
    int e = blockIdx.x * blockDim.x + threadIdx.x;
    if (e < N_EDGES) {
        int pos = atomicAdd(&g_cursor[dst[e]], 1);
        g_csr_src[pos] = src[e];
    }
}

// ---------------- weight prep: fp32 W[k][n] -> bf16 hi/lo in [n][k] ----------------
__global__ void convw_kernel(const float* __restrict__ W1, const float* __restrict__ W2,
                             const float* __restrict__ W3) {
    int i = blockIdx.x * blockDim.x + threadIdx.x;
    if (i >= 3 * FEAT * FEAT) return;
    int l = i >> 14, r = i & 16383;
    int n = r >> 7, k = r & 127;
    const float* W = (l == 0) ? W1 : ((l == 1) ? W2 : W3);
    float v = W[k * FEAT + n];
    __nv_bfloat16 h = __float2bfloat16(v);
    g_whi[i] = h;
    g_wlo[i] = __float2bfloat16(v - __bfloat162float(h));
}

// ---------------- aggregation: out = h + inv_deg * sum_{src} h[src] ----------------
__global__ void agg_kernel(const float4* __restrict__ h4, float4* __restrict__ out4) {
    int warp = (blockIdx.x * blockDim.x + threadIdx.x) >> 5;
    if (warp >= N_NODES) return;
    int lane = threadIdx.x & 31;

    int s = g_rowstart[warp];
    int e = g_rowstart[warp + 1];

    float4 acc = make_float4(0.f, 0.f, 0.f, 0.f);
    int i = s;
    for (; i + 4 <= e; i += 4) {
        int s0 = g_csr_src[i + 0];
        int s1 = g_csr_src[i + 1];
        int s2 = g_csr_src[i + 2];
        int s3 = g_csr_src[i + 3];
        float4 v0 = h4[s0 * 32 + lane];
        float4 v1 = h4[s1 * 32 + lane];
        float4 v2 = h4[s2 * 32 + lane];
        float4 v3 = h4[s3 * 32 + lane];
        acc.x += (v0.x + v1.x) + (v2.x + v3.x);
        acc.y += (v0.y + v1.y) + (v2.y + v3.y);
        acc.z += (v0.z + v1.z) + (v2.z + v3.z);
        acc.w += (v0.w + v1.w) + (v2.w + v3.w);
    }
    for (; i < e; i++) {
        int s0 = g_csr_src[i];
        float4 v = h4[s0 * 32 + lane];
        acc.x += v.x; acc.y += v.y; acc.z += v.z; acc.w += v.w;
    }

    float w = g_invdeg[warp];
    float4 self = h4[warp * 32 + lane];
    float4 o;
    o.x = self.x + acc.x * w;
    o.y = self.y + acc.y * w;
    o.z = self.z + acc.z * w;
    o.w = self.w + acc.w * w;
    out4[warp * 32 + lane] = o;
}

// ---------------- HMMA GEMM: out[M,128] = [relu](A[M,128] @ W + b) ----------------
// bf16 hi/lo split via mma.sync: D = aHi*wHi + aHi*wLo + aLo*wHi.
#define APITCH 136
#define GEMM_SMEM_BYTES (4 * 128 * APITCH * 2)

__global__ void __launch_bounds__(256, 1)
mma_gemm_kernel(const float* __restrict__ A,
                const __nv_bfloat16* __restrict__ whi,
                const __nv_bfloat16* __restrict__ wlo,
                const float* __restrict__ bias,
                float* __restrict__ out, int M, int do_relu) {
    extern __shared__ __nv_bfloat16 sm[];
    __nv_bfloat16* sAhi = sm;
    __nv_bfloat16* sAlo = sm + 128 * APITCH;
    __nv_bfloat16* sWhi = sm + 2 * 128 * APITCH;
    __nv_bfloat16* sWlo = sm + 3 * 128 * APITCH;

    const int tid  = threadIdx.x;
    const int lane = tid & 31;
    const int wid  = tid >> 5;
    const int row0 = blockIdx.x * 128;
    const int rows = min(128, M - row0);

    if (rows < 128) {
        uint32_t z = 0;
        uint32_t base = smem_u32(sAhi);
        for (int idx = tid; idx < 2 * 128 * APITCH / 2; idx += 256)
            asm volatile("st.shared.b32 [%0], %1;" :: "r"(base + idx * 4), "r"(z) : "memory");
        __syncthreads();
    }

    {
        const float4* A4 = reinterpret_cast<const float4*>(A);
        for (int idx = tid; idx < rows * 32; idx += 256) {
            int r = idx >> 5, c4 = idx & 31;
            float4 a = __ldg(&A4[(size_t)(row0 + r) * 32 + c4]);
            __nv_bfloat162 h0 = __floats2bfloat162_rn(a.x, a.y);
            __nv_bfloat162 h1 = __floats2bfloat162_rn(a.z, a.w);
            float2 f0 = __bfloat1622float2(h0);
            float2 f1 = __bfloat1622float2(h1);
            __nv_bfloat162 l0 = __floats2bfloat162_rn(a.x - f0.x, a.y - f0.y);
            __nv_bfloat162 l1 = __floats2bfloat162_rn(a.z - f1.x, a.w - f1.y);
            int eoff = r * APITCH + c4 * 4;
            *reinterpret_cast<__nv_bfloat162*>(sAhi + eoff)     = h0;
            *reinterpret_cast<__nv_bfloat162*>(sAhi + eoff + 2) = h1;
            *reinterpret_cast<__nv_bfloat162*>(sAlo + eoff)     = l0;
            *reinterpret_cast<__nv_bfloat162*>(sAlo + eoff + 2) = l1;
        }
    }

    {
        const uint4* wh4 = reinterpret_cast<const uint4*>(whi);
        const uint4* wl4 = reinterpret_cast<const uint4*>(wlo);
        for (int idx = tid; idx < 2048; idx += 256) {
            int r = idx >> 4, c16 = idx & 15;
            int eoff = r * APITCH + c16 * 8;
            *reinterpret_cast<uint4*>(sWhi + eoff) = __ldg(&wh4[idx]);
            *reinterpret_cast<uint4*>(sWlo + eoff) = __ldg(&wl4[idx]);
        }
    }
    __syncthreads();

    const int wm = wid & 3;
    const int wn = wid >> 2;

    float acc[2][8][4];
    #pragma unroll
    for (int i = 0; i < 2; i++)
        #pragma unroll
        for (int j = 0; j < 8; j++)
            #pragma unroll
            for (int c = 0; c < 4; c++) acc[i][j][c] = 0.f;

    const uint32_t aRowOff = (uint32_t)(((wm * 32 + (lane & 15)) * APITCH + (lane >> 4) * 8) * 2);
    const uint32_t bRowOff = (uint32_t)(((wn * 64 + (lane & 7)) * APITCH + ((lane >> 3) & 1) * 8) * 2);

    #pragma unroll
    for (int pass = 0; pass < 3; pass++) {
        const __nv_bfloat16* pA = (pass == 2) ? sAlo : sAhi;
        const __nv_bfloat16* pW = (pass == 1) ? sWlo : sWhi;
        uint32_t aAddr = smem_u32(pA) + aRowOff;
        uint32_t bAddr = smem_u32(pW) + bRowOff;

        #pragma unroll
        for (int kk = 0; kk < 8; kk++) {
            uint32_t a0[4], a1[4];
            ldmatrix_x4(a0, aAddr + kk * 32);
            ldmatrix_x4(a1, aAddr + 16 * APITCH * 2 + kk * 32);
            #pragma unroll
            for (int tn = 0; tn < 8; tn++) {
                uint32_t b[2];
                ldmatrix_x2(b, bAddr + tn * 8 * APITCH * 2 + kk * 32);
                mma16816(acc[0][tn], a0, b);
                mma16816(acc[1][tn], a1, b);
            }
        }
    }

    #pragma unroll
    for (int tm = 0; tm < 2; tm++) {
        int rbase = wm * 32 + tm * 16 + (lane >> 2);
        #pragma unroll
        for (int half = 0; half < 2; half++) {
            int r = rbase + half * 8;
            if (r < rows) {
                float* orow = out + (size_t)(row0 + r) * 128;
                #pragma unroll
                for (int tn = 0; tn < 8; tn++) {
                    int c = wn * 64 + tn * 8 + (lane & 3) * 2;
                    float2 o;
                    o.x = acc[tm][tn][half * 2 + 0] + __ldg(&bias[c + 0]);
                    o.y = acc[tm][tn][half * 2 + 1] + __ldg(&bias[c + 1]);
                    if (do_relu) { o.x = fmaxf(o.x, 0.f); o.y = fmaxf(o.y, 0.f); }
                    *reinterpret_cast<float2*>(orow + c) = o;
                }
            }
        }
    }
}

// ---------------- launch ----------------
extern "C" void kernel_launch(void* const* d_in, const int* in_sizes, int n_in,
                              void* d_out, int out_size) {
    const float* x        = (const float*)d_in[0];
    const float* W1       = (const float*)d_in[1];
    const float* b1       = (const float*)d_in[2];
    const float* W2       = (const float*)d_in[3];
    const float* b2       = (const float*)d_in[4];
    const float* W3       = (const float*)d_in[5];
    const float* b3       = (const float*)d_in[6];
    const int*   edge_src = (const int*)d_in[7];
    const int*   edge_dst = (const int*)d_in[8];
    float* out = (float*)d_out;

    (void)in_sizes; (void)n_in; (void)out_size;

    cudaFuncSetAttribute(mma_gemm_kernel,
                         cudaFuncAttributeMaxDynamicSharedMemorySize, GEMM_SMEM_BYTES);

    float* bufA; float* bufB;
    __nv_bfloat16* whi; __nv_bfloat16* wlo;
    cudaGetSymbolAddress((void**)&bufA, g_bufA);
    cudaGetSymbolAddress((void**)&bufB, g_bufB);
    cudaGetSymbolAddress((void**)&whi, g_whi);
    cudaGetSymbolAddress((void**)&wlo, g_wlo);

    const int M = N_NODES;
    const int edgeBlocks = (N_EDGES + 255) / 256;
    const int nodeBlocks = (N_NODES + 255) / 256;
    const int aggBlocks  = (N_NODES * 32 + 255) / 256;
    const int gemmBlocks = (M + 127) / 128;

    // weight prep (independent; overlaps CSR build)
    convw_kernel<<<(3 * FEAT * FEAT + 255) / 256, 256>>>(W1, W2, W3);

    // CSR build (parallel 3-pass scan)
    zero_cursor_kernel<<<nodeBlocks, 256>>>();
    hist_kernel<<<edgeBlocks, 256>>>(edge_dst);
    scan_reduce_kernel<<<SCAN_NBLK, 256>>>();
    scan_blocksums_kernel<<<1, 256>>>();
    scan_write_kernel<<<SCAN_NBLK, SCAN_BLK>>>();
    scatter_kernel<<<edgeBlocks, 256>>>(edge_src, edge_dst);

    // layer 1
    agg_kernel<<<aggBlocks, 256>>>((const float4*)x, (float4*)bufA);
    mma_gemm_kernel<<<gemmBlocks, 256, GEMM_SMEM_BYTES>>>(bufA, whi, wlo, b1, bufB, M, 1);
    // layer 2
    agg_kernel<<<aggBlocks, 256>>>((const float4*)bufB, (float4*)bufA);
    mma_gemm_kernel<<<gemmBlocks, 256, GEMM_SMEM_BYTES>>>(bufA, whi + FEAT * FEAT, wlo + FEAT * FEAT, b2, bufB, M, 1);
    // layer 3
    agg_kernel<<<aggBlocks, 256>>>((const float4*)bufB, (float4*)bufA);
    mma_gemm_kernel<<<gemmBlocks, 256, GEMM_SMEM_BYTES>>>(bufA, whi + 2 * FEAT * FEAT, wlo + 2 * FEAT * FEAT, b3, out, M, 0);
}